// round 8
// baseline (speedup 1.0000x reference)
#include <cuda_runtime.h>

#define B_  32
#define D_  32
#define H_  256
#define W_  256
#define K_  512
#define TT  64                     // pair-tile size
#define NT  (K_ / TT)              // 8 tiles per image
#define NPAIRS (NT * (NT + 1) / 2) // 36 (ti <= tj)
#define GTHREADS 256
#define LTHREADS 128               // loss: 16(kg) x 8(lg), 4x8 regs each

typedef unsigned long long ull;

// Scratch: gathered pred, TRANSPOSED [B][D][K] (k contiguous), norms, tags.
__device__ float g_predT[B_ * D_ * K_];  // 2 MB
__device__ float g_ns[B_ * K_];
__device__ int   g_tag[B_ * K_];

__device__ __forceinline__ float tanh_approx(float x) {
    float y;
    asm("tanh.approx.f32 %0, %1;" : "=f"(y) : "f"(x));
    return y;
}
__device__ __forceinline__ ull pack2(float lo, float hi) {
    ull r;
    asm("mov.b64 %0, {%1, %2};" : "=l"(r) : "f"(lo), "f"(hi));
    return r;
}
__device__ __forceinline__ void fma2(ull& acc, ull a, ull b) {
    asm("fma.rn.f32x2 %0, %1, %2, %0;" : "+l"(acc) : "l"(a), "l"(b));
}

union F4U { float4 f; ull u[2]; };
union UF  { ull u; float f[2]; };

// Four threads per (b, k): each gathers 8 channels, writes d-major,
// partial ||p||^2 combined via 2-stage shfl. dtype (int32 vs int64)
// detected from data: int64 => high dword of every value is 0.
__global__ void gather_kernel(const float* __restrict__ ebd,
                              const void* __restrict__ kpts_raw,
                              const void* __restrict__ tags_raw,
                              float* __restrict__ out) {
    if (blockIdx.x == 0 && threadIdx.x == 0) out[0] = 0.0f;

    int tid = blockIdx.x * blockDim.x + threadIdx.x;   // 4*(b*K + k) + h
    if (tid >= B_ * K_ * 4) return;
    int idx = tid >> 2;            // point index b*K + k
    int h   = tid & 3;             // d-quarter

    const unsigned* kd = (const unsigned*)kpts_raw;
    bool is64 = true;
#pragma unroll
    for (int i = 1; i < 32; i += 2) is64 &= (__ldg(kd + i) == 0u);

    int r, c, tg;
    if (is64) {
        const long long* kp  = (const long long*)kpts_raw;
        const long long* tgp = (const long long*)tags_raw;
        r  = (int)kp[(size_t)idx * 2 + 0];
        c  = (int)kp[(size_t)idx * 2 + 1];
        tg = (int)tgp[idx];
    } else {
        const int* kp  = (const int*)kpts_raw;
        const int* tgp = (const int*)tags_raw;
        r  = kp[(size_t)idx * 2 + 0];
        c  = kp[(size_t)idx * 2 + 1];
        tg = tgp[idx];
    }
    r = min(max(r, 0), H_ - 1);
    c = min(max(c, 0), W_ - 1);

    int b = idx >> 9;
    int k = idx & (K_ - 1);
    const int d0 = h * (D_ / 4);
    const float* base = ebd + (size_t)b * D_ * H_ * W_ + (size_t)d0 * (H_ * W_)
                            + (size_t)r * W_ + (size_t)c;
    float* dstT = g_predT + (size_t)b * D_ * K_ + (size_t)d0 * K_ + k;
    float ns = 0.0f;
#pragma unroll
    for (int d = 0; d < D_ / 4; ++d) {
        float x = base[(size_t)d * (H_ * W_)];
        dstT[(size_t)d * K_] = x;
        ns += x * x;
    }
    ns += __shfl_xor_sync(0xffffffffu, ns, 1);
    ns += __shfl_xor_sync(0xffffffffu, ns, 2);
    if (h == 0) {
        g_ns[idx]  = ns;
        g_tag[idx] = tg;
    }
}

// Symmetry-halved pairwise loss, 4(k)x8(l) register micro-GEMM on 128
// threads (16 k-groups x 8 l-groups), packed fma.rn.f32x2 along l.
// Thread t: k in {k0..k0+3} (k0=(t&15)*4),
//           l in {l0..l0+3, l0+32..l0+35} (l0=(t>>4)*4).
// psim = 2/(1+exp(x)) = 1 - tanh(x/2)  ->  e = tanh(arg) - neq.
__global__ __launch_bounds__(LTHREADS) void loss_kernel(float* __restrict__ out) {
    const int b = blockIdx.x / NPAIRS;
    int p = blockIdx.x % NPAIRS;
    int ti = 0;
    while (p >= NT - ti) { p -= (NT - ti); ++ti; }
    const int tj = ti + p;

    __shared__ float sI[D_ * TT];   // [d][k] 8 KB
    __shared__ float sJ[D_ * TT];   // [d][l] 8 KB
    __shared__ float nsI[TT], nsJ[TT];
    __shared__ int   tgI[TT], tgJ[TT];
    __shared__ float wsum[LTHREADS / 32];

    const int t = threadIdx.x;
    const float* srcI = g_predT + (size_t)b * D_ * K_ + ti * TT;
    const float* srcJ = g_predT + (size_t)b * D_ * K_ + tj * TT;

    // Fill: 512 float4 per tile, 4 per thread. Row d = 16 float4.
#pragma unroll
    for (int rr = 0; rr < 4; ++rr) {
        int idx4 = t + rr * LTHREADS;     // 0..511
        int d  = idx4 >> 4;
        int j4 = idx4 & 15;
        ((float4*)sI)[idx4] = *(const float4*)(srcI + (size_t)d * K_ + j4 * 4);
        ((float4*)sJ)[idx4] = *(const float4*)(srcJ + (size_t)d * K_ + j4 * 4);
    }
    {
        const int baseI = b * K_ + ti * TT;
        const int baseJ = b * K_ + tj * TT;
        if (t < TT) {
            nsI[t] = g_ns[baseI + t];    tgI[t] = g_tag[baseI + t];
        } else {
            nsJ[t - TT] = g_ns[baseJ + t - TT];
            tgJ[t - TT] = g_tag[baseJ + t - TT];
        }
    }
    __syncthreads();

    const int k0 = (t & 15) * 4;
    const int l0 = (t >> 4) * 4;

    // acc2[i][jp]: k_{k0+i} x packed l-pair jp:
    //   jp0 -> (l0, l0+1), jp1 -> (l0+2, l0+3),
    //   jp2 -> (l0+32, l0+33), jp3 -> (l0+34, l0+35).
    ull acc2[4][4];
#pragma unroll
    for (int i = 0; i < 4; ++i)
#pragma unroll
        for (int j = 0; j < 4; ++j) acc2[i][j] = 0ull;

    const float* pI = sI + k0;
    const float* pJ = sJ + l0;
#pragma unroll 4
    for (int d = 0; d < D_; ++d) {
        float4 ka = *(const float4*)(pI + d * TT);
        F4U b0, b1;
        b0.f = *(const float4*)(pJ + d * TT);        // broadcast in warp
        b1.f = *(const float4*)(pJ + d * TT + 32);   // broadcast in warp
        ull lu[4] = {b0.u[0], b0.u[1], b1.u[0], b1.u[1]};
        ull kd2[4] = {pack2(ka.x, ka.x), pack2(ka.y, ka.y),
                      pack2(ka.z, ka.z), pack2(ka.w, ka.w)};
#pragma unroll
        for (int i = 0; i < 4; ++i)
#pragma unroll
            for (int j = 0; j < 4; ++j)
                fma2(acc2[i][j], kd2[i], lu[j]);
    }

    // Epilogue: 32 pairs. arg = (nsk + nsl - 2*dot)/64; e = tanh(arg) - neq.
    float nsk2[4], nsl2[8];
    int   tgk[4], tgl[8];
#pragma unroll
    for (int i = 0; i < 4; ++i) {
        nsk2[i] = nsI[k0 + i] * (1.0f / 64.0f);
        tgk[i]  = tgI[k0 + i];
        nsl2[i]     = nsJ[l0 + i]      * (1.0f / 64.0f);
        nsl2[i + 4] = nsJ[l0 + 32 + i] * (1.0f / 64.0f);
        tgl[i]      = tgJ[l0 + i];
        tgl[i + 4]  = tgJ[l0 + 32 + i];
    }

    float lsum = 0.0f;
#pragma unroll
    for (int i = 0; i < 4; ++i) {
#pragma unroll
        for (int jp = 0; jp < 4; ++jp) {
            UF v; v.u = acc2[i][jp];
            int j0 = (jp < 2) ? (2 * jp) : (4 + 2 * (jp - 2));
            int j1 = j0 + 1;
            float arg0 = fmaf(v.f[0], -1.0f / 32.0f, nsk2[i] + nsl2[j0]);
            float arg1 = fmaf(v.f[1], -1.0f / 32.0f, nsk2[i] + nsl2[j1]);
            float e0 = tanh_approx(arg0) - ((tgk[i] != tgl[j0]) ? 1.0f : 0.0f);
            float e1 = tanh_approx(arg1) - ((tgk[i] != tgl[j1]) ? 1.0f : 0.0f);
            lsum += e0 * e0 + e1 * e1;
        }
    }

    // Block reduction (4 warps) + weighted atomic.
#pragma unroll
    for (int o = 16; o > 0; o >>= 1)
        lsum += __shfl_down_sync(0xffffffffu, lsum, o);
    if ((t & 31) == 0) wsum[t >> 5] = lsum;
    __syncthreads();
    if (t == 0) {
        float w = (ti == tj) ? 1.0f : 2.0f;
        float s = wsum[0] + wsum[1] + wsum[2] + wsum[3];
        atomicAdd(out, s * w * (1.0f / ((float)B_ * (float)K_ * (float)K_)));
    }
}

extern "C" void kernel_launch(void* const* d_in, const int* in_sizes, int n_in,
                              void* d_out, int out_size) {
    const float* ebd  = (const float*)d_in[0];
    const void*  kpts = (const void*)d_in[1];
    const void*  tags = (const void*)d_in[2];
    float* out = (float*)d_out;

    (void)in_sizes; (void)n_in; (void)out_size;

    gather_kernel<<<(B_ * K_ * 4 + GTHREADS - 1) / GTHREADS, GTHREADS>>>(ebd, kpts, tags, out);
    loss_kernel<<<B_ * NPAIRS, LTHREADS>>>(out);
}